// round 11
// baseline (speedup 1.0000x reference)
#include <cuda_runtime.h>
#include <math.h>

#define L   12288
#define BB  8
#define NI  48                    // i-chunks
#define CHUNK (L / NI)            // 256 rows per chunk
#define THREADS 256
#define GX  (L / THREADS)         // 48 column-blocks (1 col/thread)
#define RB  8                     // row batch
#define NB  (CHUNK / RB)          // 32 batches per chunk
#define DEPTH 4                   // cp.async ring depth
#define GX2 (L / 32)              // 384 pass2 blocks

// Scratch (static device globals — allocation-free)
__device__ float g_part[NI][BB][L];   // partial candidate sums (~18.9 MB)
__device__ float g_cnt[NI][L];        // partial counts
__device__ float g_bpart[GX2][BB];    // pass2 per-block squared-diff sums

__device__ __forceinline__ void cp_async16(void* s, const void* g) {
    unsigned sa = (unsigned)__cvta_generic_to_shared(s);
    asm volatile("cp.async.cg.shared.global [%0], [%1], 16;" :: "r"(sa), "l"(g));
}
__device__ __forceinline__ void cp_commit() {
    asm volatile("cp.async.commit_group;" ::: "memory");
}
template <int N>
__device__ __forceinline__ void cp_wait() {
    asm volatile("cp.async.wait_group %0;" :: "n"(N) : "memory");
}

// ---------------------------------------------------------------------------
// Pass 1: partial  cand[b][j] = sum_{i in chunk} mask[i][j] * adj[i][j] * p[b][i]
//         partial  cnt[j]     = sum_{i in chunk} mask[i][j]
// Mask stream: cp.async smem ring (depth 4, ~3-iter prefetch distance).
// Adj stream: predicated LDG gathered 1 batch ahead, sentinel -1 (adj >= 0).
// ---------------------------------------------------------------------------
__global__ __launch_bounds__(THREADS, 5)
void pass1_kernel(const float* __restrict__ predicts,
                  const float* __restrict__ adj,
                  const int* __restrict__ mask) {
    __shared__ float sp[CHUNK][BB];               // 8 KB, row-contiguous
    __shared__ int   smask[DEPTH][RB][THREADS];   // 32 KB mask ring

    const int t     = threadIdx.x;
    const int jbase = blockIdx.x * THREADS;
    const int j     = jbase + t;                  // this thread's column
    const int chunk = blockIdx.y;
    const int i0    = chunk * CHUNK;

    // cp.async mapping: thread t fills row (t>>5), 2x16B at cols (t&31)*4 (+128)
    const int crow = t >> 5;
    const int ccol = (t & 31) * 4;
    const int* gmask_base = mask + (size_t)(i0 + crow) * L + jbase;

    float acc[BB];
    float cnt = 0.f;
#pragma unroll
    for (int b = 0; b < BB; ++b) acc[b] = 0.f;

    // predicts tile transposed (CHUNK == 256 == THREADS)
#pragma unroll
    for (int b = 0; b < BB; ++b)
        sp[t][b] = predicts[b * L + i0 + t];

    // ---- prologue: issue mask batches 0..3 ----
#pragma unroll
    for (int q = 0; q < DEPTH; ++q) {
        const int* g = gmask_base + (size_t)(q * RB) * L;
        cp_async16(&smask[q][crow][ccol],       g + ccol);
        cp_async16(&smask[q][crow][ccol + 128], g + ccol + 128);
        cp_commit();
    }

    cp_wait<3>();            // batch 0 resident
    __syncthreads();         // visible block-wide (also covers sp)

    const float* ap = adj + (size_t)i0 * L + j;
    float a_cur[RB], a_next[RB];
#pragma unroll
    for (int r = 0; r < RB; ++r)
        a_cur[r] = smask[0][r][t] ? __ldcs(ap + (size_t)r * L) : -1.0f;

    // ---- steady state ----
    for (int k = 0; k < NB; ++k) {
        cp_wait<2>();        // batch k+1 resident (groups done through k+1)
        __syncthreads();

        if (k + 1 < NB) {
            const int slot = (k + 1) % DEPTH;
            const float* apn = ap + (size_t)RB * L;
#pragma unroll
            for (int r = 0; r < RB; ++r)
                a_next[r] = smask[slot][r][t] ? __ldcs(apn + (size_t)r * L) : -1.0f;
        }

        // consume batch k (gathered last iteration)
        const int ii = k * RB;
#pragma unroll
        for (int r = 0; r < RB; ++r) {
            const float a = a_cur[r];
            if (a >= 0.0f) {
                cnt += 1.f;
                const float4 lo = *(const float4*)&sp[ii + r][0];
                const float4 hi = *(const float4*)&sp[ii + r][4];
                acc[0] = fmaf(lo.x, a, acc[0]);
                acc[1] = fmaf(lo.y, a, acc[1]);
                acc[2] = fmaf(lo.z, a, acc[2]);
                acc[3] = fmaf(lo.w, a, acc[3]);
                acc[4] = fmaf(hi.x, a, acc[4]);
                acc[5] = fmaf(hi.y, a, acc[5]);
                acc[6] = fmaf(hi.z, a, acc[6]);
                acc[7] = fmaf(hi.w, a, acc[7]);
            }
        }

        // issue mask batch k+4 into slot k%DEPTH (consumed slot, safe after barrier)
        if (k + DEPTH < NB) {
            const int slot = k % DEPTH;
            const int* g = gmask_base + (size_t)((k + DEPTH) * RB) * L;
            cp_async16(&smask[slot][crow][ccol],       g + ccol);
            cp_async16(&smask[slot][crow][ccol + 128], g + ccol + 128);
        }
        cp_commit();         // always commit (possibly empty) to keep counts uniform

        ap += (size_t)RB * L;
#pragma unroll
        for (int r = 0; r < RB; ++r) a_cur[r] = a_next[r];
    }

    g_cnt[chunk][j] = cnt;
#pragma unroll
    for (int b = 0; b < BB; ++b)
        g_part[chunk][b][j] = acc[b];
}

// ---------------------------------------------------------------------------
// Pass 2: thread = (b, j) pair. 256 threads = 8 b-groups x 32 j-lanes.
// ---------------------------------------------------------------------------
__global__ __launch_bounds__(256)
void pass2_kernel(const float* __restrict__ predicts,
                  const float* __restrict__ sim,
                  const int* __restrict__ mask) {
    __shared__ float ssim[BB * BB];
    __shared__ float scand[BB][33];
    __shared__ float sadd[32], sinv[32];

    const int t  = threadIdx.x;
    const int b  = t >> 5;
    const int jl = t & 31;
    const int j  = blockIdx.x * 32 + jl;

    if (t < BB * BB) ssim[t] = sim[t];

    if (b == 0) {
        float cnt = 0.f;
#pragma unroll
        for (int c = 0; c < NI; ++c) cnt += g_cnt[c][j];
        const float mjj = mask[(size_t)j * (L + 1)] ? 1.f : 0.f;
        const float add = 1.f - mjj;
        sadd[jl] = add;
        sinv[jl] = 1.f / (cnt + add);
    }

    float acc = 0.f;
#pragma unroll
    for (int c = 0; c < NI; ++c) acc += g_part[c][b][j];
    const float p = predicts[b * L + j];
    __syncthreads();

    const float cand = (acc + p * sadd[jl]) * sinv[jl];
    scand[b][jl] = cand;
    __syncthreads();

    float d = p;
#pragma unroll
    for (int k = 0; k < BB; ++k) d -= ssim[b * BB + k] * scand[k][jl];
    float ss = d * d;

#pragma unroll
    for (int o = 16; o > 0; o >>= 1) ss += __shfl_down_sync(0xffffffffu, ss, o);
    if (jl == 0) g_bpart[blockIdx.x][b] = ss;
}

// ---------------------------------------------------------------------------
// Pass 3: final reduce: norms = sqrt(sumsq), valid mask, mean over valid.
// ---------------------------------------------------------------------------
__global__ __launch_bounds__(256)
void pass3_kernel(const float* __restrict__ sim, float* __restrict__ out) {
    __shared__ float norms[BB];
    const int w    = threadIdx.x >> 5;
    const int lane = threadIdx.x & 31;

    if (w < BB) {
        float s = 0.f;
        for (int i = lane; i < GX2; i += 32) s += g_bpart[i][w];
#pragma unroll
        for (int o = 16; o > 0; o >>= 1) s += __shfl_down_sync(0xffffffffu, s, o);
        if (lane == 0) norms[w] = sqrtf(s);
    }
    __syncthreads();

    if (threadIdx.x == 0) {
        float total = 0.f, c = 0.f;
        for (int b = 0; b < BB; ++b) {
            float rs = 0.f;
            for (int k = 0; k < BB; ++k) rs += sim[b * BB + k];
            if (rs != 0.f) { c += 1.f; total += norms[b]; }
        }
        out[0] = (c == 0.f) ? 0.f : total / fmaxf(c, 1.f);
    }
}

// ---------------------------------------------------------------------------
extern "C" void kernel_launch(void* const* d_in, const int* in_sizes, int n_in,
                              void* d_out, int out_size) {
    (void)in_sizes; (void)n_in; (void)out_size;
    const float* predicts = (const float*)d_in[0];   // [8, L]
    const float* sim      = (const float*)d_in[1];   // [8, 8]
    const float* adj      = (const float*)d_in[2];   // [L, L]
    const int*   mask     = (const int*)d_in[3];     // [L, L] bool->int32
    float* out = (float*)d_out;

    dim3 g1(GX, NI);
    pass1_kernel<<<g1, THREADS>>>(predicts, adj, mask);
    pass2_kernel<<<GX2, 256>>>(predicts, sim, mask);
    pass3_kernel<<<1, 256>>>(sim, out);
}

// round 12
// speedup vs baseline: 1.0044x; 1.0044x over previous
#include <cuda_runtime.h>
#include <math.h>

#define L   12288
#define BB  8
#define NI  48                    // i-chunks
#define CHUNK (L / NI)            // 256 rows per chunk
#define THREADS 256
#define WARPS (THREADS / 32)
#define GX  (L / THREADS)         // 48 column-blocks (1 col/thread)
#define RB  8                     // row batch
#define NB  (CHUNK / RB)          // 32 batches per chunk
#define DEPTH 4                   // cp.async ring depth (NB % DEPTH == 0)
#define GX2 (L / 32)              // 384 pass2 blocks

// Scratch (static device globals — allocation-free)
__device__ float g_part[NI][BB][L];   // partial candidate sums (~18.9 MB)
__device__ float g_cnt[NI][L];        // partial counts
__device__ float g_bpart[GX2][BB];    // pass2 per-block squared-diff sums

__device__ __forceinline__ void cp_async16(void* s, const void* g) {
    unsigned sa = (unsigned)__cvta_generic_to_shared(s);
    asm volatile("cp.async.cg.shared.global [%0], [%1], 16;" :: "r"(sa), "l"(g));
}
__device__ __forceinline__ void cp_commit() {
    asm volatile("cp.async.commit_group;" ::: "memory");
}
template <int N>
__device__ __forceinline__ void cp_wait() {
    asm volatile("cp.async.wait_group %0;" :: "n"(N) : "memory");
}

// ---------------------------------------------------------------------------
// Pass 1: partial  cand[b][j] = sum_{i in chunk} mask[i][j] * adj[i][j] * p[b][i]
//         partial  cnt[j]     = sum_{i in chunk} mask[i][j]
// Warp-private cp.async mask rings (no block barriers in the main loop),
// steady loop unrolled by DEPTH (compile-time slots), adj gathered 1 batch
// ahead with 0.0 sentinel, counts accumulated as integers from the mask.
// ---------------------------------------------------------------------------
__global__ __launch_bounds__(THREADS, 5)
void pass1_kernel(const float* __restrict__ predicts,
                  const float* __restrict__ adj,
                  const int* __restrict__ mask) {
    __shared__ float sp[CHUNK][BB];                  // 8 KB predicts tile
    __shared__ int   smask[WARPS][DEPTH][RB][32];    // 32 KB warp-private rings

    const int t     = threadIdx.x;
    const int l     = t & 31;
    const int w     = t >> 5;
    const int jbase = blockIdx.x * THREADS;
    const int j     = jbase + t;                     // this thread's column
    const int chunk = blockIdx.y;
    const int i0    = chunk * CHUNK;

    // cp.async mapping (per warp, per batch: 8 rows x 128B):
    // lane l copies 16B of rows (l>>3) and (l>>3)+4 at column-seg (l&7)*4 ints
    const int r0  = l >> 3;
    const int sg  = (l & 7) * 4;
    const int* gw = mask + (size_t)i0 * L + jbase + w * 32 + sg;

    float acc[BB];
    int   cnt = 0;
#pragma unroll
    for (int b = 0; b < BB; ++b) acc[b] = 0.f;

    // predicts tile transposed (CHUNK == 256 == THREADS)
#pragma unroll
    for (int b = 0; b < BB; ++b)
        sp[t][b] = predicts[b * L + i0 + t];

    // ---- prologue: issue mask batches 0..DEPTH-1 into this warp's ring ----
#pragma unroll
    for (int q = 0; q < DEPTH; ++q) {
        cp_async16(&smask[w][q][r0][sg],     gw + (size_t)(q * RB + r0) * L);
        cp_async16(&smask[w][q][r0 + 4][sg], gw + (size_t)(q * RB + r0 + 4) * L);
        cp_commit();
    }

    __syncthreads();          // sp visible block-wide (one-time barrier)
    cp_wait<3>();             // batch 0 resident
    __syncwarp();

    const float* ap = adj + (size_t)i0 * L + j;
    float a_cur[RB], a_next[RB];
#pragma unroll
    for (int r = 0; r < RB; ++r) {
        const int m = smask[w][0][r][l];
        cnt += m;
        a_cur[r] = m ? __ldcs(ap + (size_t)r * L) : 0.0f;
    }

    // ---- steady state: unrolled by DEPTH so ring slots are constants ----
    for (int kb = 0; kb < NB; kb += DEPTH) {
#pragma unroll
        for (int u = 0; u < DEPTH; ++u) {
            const int k = kb + u;

            cp_wait<2>();     // batch k+1 resident in this warp's ring
            __syncwarp();

            if (k + 1 < NB) { // gather adj for batch k+1 (slot (u+1)%DEPTH)
                const float* apn = ap + (size_t)RB * L;
#pragma unroll
                for (int r = 0; r < RB; ++r) {
                    const int m = smask[w][(u + 1) % DEPTH][r][l];
                    cnt += m;
                    a_next[r] = m ? __ldcs(apn + (size_t)r * L) : 0.0f;
                }
            }

            // consume batch k (adj gathered one iteration ago)
            const int ii = k * RB;
#pragma unroll
            for (int r = 0; r < RB; ++r) {
                const float a = a_cur[r];
                if (a != 0.0f) {
                    const float4 lo = *(const float4*)&sp[ii + r][0];
                    const float4 hi = *(const float4*)&sp[ii + r][4];
                    acc[0] = fmaf(lo.x, a, acc[0]);
                    acc[1] = fmaf(lo.y, a, acc[1]);
                    acc[2] = fmaf(lo.z, a, acc[2]);
                    acc[3] = fmaf(lo.w, a, acc[3]);
                    acc[4] = fmaf(hi.x, a, acc[4]);
                    acc[5] = fmaf(hi.y, a, acc[5]);
                    acc[6] = fmaf(hi.z, a, acc[6]);
                    acc[7] = fmaf(hi.w, a, acc[7]);
                }
            }

            // refill slot u with batch k+DEPTH (this warp's masks fully read)
            if (k + DEPTH < NB) {
                const size_t roff = (size_t)((k + DEPTH) * RB) * L;
                cp_async16(&smask[w][u][r0][sg],     gw + roff + (size_t)r0 * L);
                cp_async16(&smask[w][u][r0 + 4][sg], gw + roff + (size_t)(r0 + 4) * L);
            }
            cp_commit();      // uniform group count even on tail iterations

            ap += (size_t)RB * L;
#pragma unroll
            for (int r = 0; r < RB; ++r) a_cur[r] = a_next[r];
        }
    }

    g_cnt[chunk][j] = (float)cnt;
#pragma unroll
    for (int b = 0; b < BB; ++b)
        g_part[chunk][b][j] = acc[b];
}

// ---------------------------------------------------------------------------
// Pass 2: thread = (b, j) pair. 256 threads = 8 b-groups x 32 j-lanes.
// ---------------------------------------------------------------------------
__global__ __launch_bounds__(256)
void pass2_kernel(const float* __restrict__ predicts,
                  const float* __restrict__ sim,
                  const int* __restrict__ mask) {
    __shared__ float ssim[BB * BB];
    __shared__ float scand[BB][33];
    __shared__ float sadd[32], sinv[32];

    const int t  = threadIdx.x;
    const int b  = t >> 5;
    const int jl = t & 31;
    const int j  = blockIdx.x * 32 + jl;

    if (t < BB * BB) ssim[t] = sim[t];

    if (b == 0) {
        float cnt = 0.f;
#pragma unroll
        for (int c = 0; c < NI; ++c) cnt += g_cnt[c][j];
        const float mjj = mask[(size_t)j * (L + 1)] ? 1.f : 0.f;
        const float add = 1.f - mjj;
        sadd[jl] = add;
        sinv[jl] = 1.f / (cnt + add);
    }

    float acc = 0.f;
#pragma unroll
    for (int c = 0; c < NI; ++c) acc += g_part[c][b][j];
    const float p = predicts[b * L + j];
    __syncthreads();

    const float cand = (acc + p * sadd[jl]) * sinv[jl];
    scand[b][jl] = cand;
    __syncthreads();

    float d = p;
#pragma unroll
    for (int k = 0; k < BB; ++k) d -= ssim[b * BB + k] * scand[k][jl];
    float ss = d * d;

#pragma unroll
    for (int o = 16; o > 0; o >>= 1) ss += __shfl_down_sync(0xffffffffu, ss, o);
    if (jl == 0) g_bpart[blockIdx.x][b] = ss;
}

// ---------------------------------------------------------------------------
// Pass 3: final reduce: norms = sqrt(sumsq), valid mask, mean over valid.
// ---------------------------------------------------------------------------
__global__ __launch_bounds__(256)
void pass3_kernel(const float* __restrict__ sim, float* __restrict__ out) {
    __shared__ float norms[BB];
    const int w    = threadIdx.x >> 5;
    const int lane = threadIdx.x & 31;

    if (w < BB) {
        float s = 0.f;
        for (int i = lane; i < GX2; i += 32) s += g_bpart[i][w];
#pragma unroll
        for (int o = 16; o > 0; o >>= 1) s += __shfl_down_sync(0xffffffffu, s, o);
        if (lane == 0) norms[w] = sqrtf(s);
    }
    __syncthreads();

    if (threadIdx.x == 0) {
        float total = 0.f, c = 0.f;
        for (int b = 0; b < BB; ++b) {
            float rs = 0.f;
            for (int k = 0; k < BB; ++k) rs += sim[b * BB + k];
            if (rs != 0.f) { c += 1.f; total += norms[b]; }
        }
        out[0] = (c == 0.f) ? 0.f : total / fmaxf(c, 1.f);
    }
}

// ---------------------------------------------------------------------------
extern "C" void kernel_launch(void* const* d_in, const int* in_sizes, int n_in,
                              void* d_out, int out_size) {
    (void)in_sizes; (void)n_in; (void)out_size;
    const float* predicts = (const float*)d_in[0];   // [8, L]
    const float* sim      = (const float*)d_in[1];   // [8, 8]
    const float* adj      = (const float*)d_in[2];   // [L, L]
    const int*   mask     = (const int*)d_in[3];     // [L, L] bool->int32
    float* out = (float*)d_out;

    dim3 g1(GX, NI);
    pass1_kernel<<<g1, THREADS>>>(predicts, adj, mask);
    pass2_kernel<<<GX2, 256>>>(predicts, sim, mask);
    pass3_kernel<<<1, 256>>>(sim, out);
}

// round 13
// speedup vs baseline: 1.1190x; 1.1141x over previous
#include <cuda_runtime.h>
#include <math.h>

#define L   12288
#define BB  8
#define NI  24                    // i-chunks
#define CHUNK (L / NI)            // 512 rows per chunk
#define THREADS 256
#define WARPS (THREADS / 32)
#define GX  (L / THREADS)         // 48 column-blocks (1 col/thread)
#define RB  8                     // row batch
#define NB  (CHUNK / RB)          // 64 batches per chunk
#define DEPTH 4                   // cp.async ring depth (NB % DEPTH == 0)
#define GX2 (L / 32)              // 384 pass2 blocks

// Scratch (static device globals — allocation-free)
__device__ float g_part[NI][BB][L];   // partial candidate sums (~9.4 MB)
__device__ float g_cnt[NI][L];        // partial counts
__device__ float g_bpart[GX2][BB];    // pass2 per-block squared-diff sums
__device__ unsigned g_ticket;         // pass2 completion ticket (self-resetting)

__device__ __forceinline__ void cp_async16(void* s, const void* g) {
    unsigned sa = (unsigned)__cvta_generic_to_shared(s);
    asm volatile("cp.async.cg.shared.global [%0], [%1], 16;" :: "r"(sa), "l"(g));
}
__device__ __forceinline__ void cp_commit() {
    asm volatile("cp.async.commit_group;" ::: "memory");
}
template <int N>
__device__ __forceinline__ void cp_wait() {
    asm volatile("cp.async.wait_group %0;" :: "n"(N) : "memory");
}

// ---------------------------------------------------------------------------
// Pass 1: partial  cand[b][j] = sum_{i in chunk} mask[i][j] * adj[i][j] * p[b][i]
//         partial  cnt[j]     = sum_{i in chunk} mask[i][j]
// Warp-private cp.async mask rings, DEPTH-unrolled steady loop, adj gathered
// one batch ahead (0.0 sentinel), integer counts from mask words.
// ---------------------------------------------------------------------------
__global__ __launch_bounds__(THREADS, 4)
void pass1_kernel(const float* __restrict__ predicts,
                  const float* __restrict__ adj,
                  const int* __restrict__ mask) {
    __shared__ float sp[CHUNK][BB];                  // 16 KB predicts tile
    __shared__ int   smask[WARPS][DEPTH][RB][32];    // 32 KB warp-private rings

    const int t     = threadIdx.x;
    const int l     = t & 31;
    const int w     = t >> 5;
    const int jbase = blockIdx.x * THREADS;
    const int j     = jbase + t;                     // this thread's column
    const int chunk = blockIdx.y;
    const int i0    = chunk * CHUNK;

    // cp.async mapping (per warp, per batch: 8 rows x 128B):
    // lane l copies 16B of rows (l>>3) and (l>>3)+4 at column-seg (l&7)*4 ints
    const int r0  = l >> 3;
    const int sg  = (l & 7) * 4;
    const int* gw = mask + (size_t)i0 * L + jbase + w * 32 + sg;

    float acc[BB];
    int   cnt = 0;
#pragma unroll
    for (int b = 0; b < BB; ++b) acc[b] = 0.f;

    // predicts tile transposed (CHUNK = 2 * THREADS)
    for (int s = t; s < CHUNK; s += THREADS)
#pragma unroll
        for (int b = 0; b < BB; ++b)
            sp[s][b] = predicts[b * L + i0 + s];

    // ---- prologue: issue mask batches 0..DEPTH-1 into this warp's ring ----
#pragma unroll
    for (int q = 0; q < DEPTH; ++q) {
        cp_async16(&smask[w][q][r0][sg],     gw + (size_t)(q * RB + r0) * L);
        cp_async16(&smask[w][q][r0 + 4][sg], gw + (size_t)(q * RB + r0 + 4) * L);
        cp_commit();
    }

    __syncthreads();          // sp visible block-wide (one-time barrier)
    cp_wait<3>();             // batch 0 resident
    __syncwarp();

    const float* ap = adj + (size_t)i0 * L + j;
    float a_cur[RB], a_next[RB];
#pragma unroll
    for (int r = 0; r < RB; ++r) {
        const int m = smask[w][0][r][l];
        cnt += m;
        a_cur[r] = m ? __ldcs(ap + (size_t)r * L) : 0.0f;
    }

    // ---- steady state: unrolled by DEPTH so ring slots are constants ----
    for (int kb = 0; kb < NB; kb += DEPTH) {
#pragma unroll
        for (int u = 0; u < DEPTH; ++u) {
            const int k = kb + u;

            cp_wait<2>();     // batch k+1 resident in this warp's ring
            __syncwarp();

            if (k + 1 < NB) { // gather adj for batch k+1 (slot (u+1)%DEPTH)
                const float* apn = ap + (size_t)RB * L;
#pragma unroll
                for (int r = 0; r < RB; ++r) {
                    const int m = smask[w][(u + 1) % DEPTH][r][l];
                    cnt += m;
                    a_next[r] = m ? __ldcs(apn + (size_t)r * L) : 0.0f;
                }
            }

            // consume batch k (adj gathered one iteration ago)
            const int ii = k * RB;
#pragma unroll
            for (int r = 0; r < RB; ++r) {
                const float a = a_cur[r];
                if (a != 0.0f) {
                    const float4 lo = *(const float4*)&sp[ii + r][0];
                    const float4 hi = *(const float4*)&sp[ii + r][4];
                    acc[0] = fmaf(lo.x, a, acc[0]);
                    acc[1] = fmaf(lo.y, a, acc[1]);
                    acc[2] = fmaf(lo.z, a, acc[2]);
                    acc[3] = fmaf(lo.w, a, acc[3]);
                    acc[4] = fmaf(hi.x, a, acc[4]);
                    acc[5] = fmaf(hi.y, a, acc[5]);
                    acc[6] = fmaf(hi.z, a, acc[6]);
                    acc[7] = fmaf(hi.w, a, acc[7]);
                }
            }

            // refill slot u with batch k+DEPTH (this warp's masks fully read)
            if (k + DEPTH < NB) {
                const size_t roff = (size_t)((k + DEPTH) * RB) * L;
                cp_async16(&smask[w][u][r0][sg],     gw + roff + (size_t)r0 * L);
                cp_async16(&smask[w][u][r0 + 4][sg], gw + roff + (size_t)(r0 + 4) * L);
            }
            cp_commit();      // uniform group count even on tail iterations

            ap += (size_t)RB * L;
#pragma unroll
            for (int r = 0; r < RB; ++r) a_cur[r] = a_next[r];
        }
    }

    g_cnt[chunk][j] = (float)cnt;
#pragma unroll
    for (int b = 0; b < BB; ++b)
        g_part[chunk][b][j] = acc[b];
}

// ---------------------------------------------------------------------------
// Pass 2 (fused finish): thread = (b, j) pair, 8 b-groups x 32 j-lanes.
// Last block (atomic ticket) does the final norm/valid/mean reduction.
// ---------------------------------------------------------------------------
__global__ __launch_bounds__(256)
void pass2_kernel(const float* __restrict__ predicts,
                  const float* __restrict__ sim,
                  const int* __restrict__ mask,
                  float* __restrict__ out) {
    __shared__ float ssim[BB * BB];
    __shared__ float scand[BB][33];
    __shared__ float sadd[32], sinv[32];
    __shared__ bool  is_last;

    const int t  = threadIdx.x;
    const int b  = t >> 5;
    const int jl = t & 31;
    const int j  = blockIdx.x * 32 + jl;

    if (t < BB * BB) ssim[t] = sim[t];

    if (b == 0) {
        float cnt = 0.f;
#pragma unroll
        for (int c = 0; c < NI; ++c) cnt += g_cnt[c][j];
        const float mjj = mask[(size_t)j * (L + 1)] ? 1.f : 0.f;
        const float add = 1.f - mjj;
        sadd[jl] = add;
        sinv[jl] = 1.f / (cnt + add);
    }

    float acc = 0.f;
#pragma unroll
    for (int c = 0; c < NI; ++c) acc += g_part[c][b][j];
    const float p = predicts[b * L + j];
    __syncthreads();

    const float cand = (acc + p * sadd[jl]) * sinv[jl];
    scand[b][jl] = cand;
    __syncthreads();

    float d = p;
#pragma unroll
    for (int k = 0; k < BB; ++k) d -= ssim[b * BB + k] * scand[k][jl];
    float ss = d * d;

#pragma unroll
    for (int o = 16; o > 0; o >>= 1) ss += __shfl_down_sync(0xffffffffu, ss, o);
    if (jl == 0) g_bpart[blockIdx.x][b] = ss;

    // ---- ticketed finish ----
    __threadfence();
    if (t == 0) {
        unsigned n = atomicAdd(&g_ticket, 1u);
        is_last = (n == GX2 - 1);
    }
    __syncthreads();

    if (is_last) {
        __shared__ float norms[BB];
        const int w    = t >> 5;
        const int lane = t & 31;
        if (w < BB) {
            float s = 0.f;
            for (int i = lane; i < GX2; i += 32) s += g_bpart[i][w];
#pragma unroll
            for (int o = 16; o > 0; o >>= 1) s += __shfl_down_sync(0xffffffffu, s, o);
            if (lane == 0) norms[w] = sqrtf(s);
        }
        __syncthreads();
        if (t == 0) {
            float total = 0.f, c = 0.f;
            for (int bb = 0; bb < BB; ++bb) {
                float rs = 0.f;
                for (int k = 0; k < BB; ++k) rs += ssim[bb * BB + k];
                if (rs != 0.f) { c += 1.f; total += norms[bb]; }
            }
            out[0] = (c == 0.f) ? 0.f : total / fmaxf(c, 1.f);
            g_ticket = 0;   // reset for next graph replay
        }
    }
}

// ---------------------------------------------------------------------------
extern "C" void kernel_launch(void* const* d_in, const int* in_sizes, int n_in,
                              void* d_out, int out_size) {
    (void)in_sizes; (void)n_in; (void)out_size;
    const float* predicts = (const float*)d_in[0];   // [8, L]
    const float* sim      = (const float*)d_in[1];   // [8, 8]
    const float* adj      = (const float*)d_in[2];   // [L, L]
    const int*   mask     = (const int*)d_in[3];     // [L, L] bool->int32
    float* out = (float*)d_out;

    dim3 g1(GX, NI);
    pass1_kernel<<<g1, THREADS>>>(predicts, adj, mask);
    pass2_kernel<<<GX2, 256>>>(predicts, sim, mask, out);
}